// round 11
// baseline (speedup 1.0000x reference)
#include <cuda_runtime.h>
#include <cuda_bf16.h>
#include <cstdint>

#define B_   16
#define C_   192
#define TX_  512
#define TY_  2048
#define SEG_ 32
#define K2_  384          // 2*C
#define NEG_INF_ (-1e9f)
#define CH_  16           // DP chunk rows staged in smem per phase
#define NLOAD_ 480        // dp loader lanes (15 warps)

// ---------------- scratch (device globals: no runtime allocation) ----------------
__device__ float g_B[B_ * K2_ * TX_];
__device__ float g_cvec[B_ * TX_];
__device__ float g_negcent[(size_t)B_ * TY_ * TX_];  // 64 MB
__device__ int   g_idx[B_ * TY_];
__device__ int   g_cnt[B_ * 16];                     // per (b, 256-row band) completed n-tiles (target 4)

// ---------------- helpers ----------------
union F2 { float2 f; unsigned long long u; };

__device__ __forceinline__ unsigned long long ffma2(unsigned long long a,
                                                    unsigned long long b,
                                                    unsigned long long c) {
    unsigned long long d;
    asm("fma.rn.f32x2 %0, %1, %2, %3;" : "=l"(d) : "l"(a), "l"(b), "l"(c));
    return d;
}

__device__ __forceinline__ int ld_acq(const int* p) {
    int v;
    asm volatile("ld.acquire.gpu.global.b32 %0, [%1];" : "=r"(v) : "l"(p) : "memory");
    return v;
}

#define CP_ASYNC16(smem_u32, gptr) \
    asm volatile("cp.async.cg.shared.global [%0], [%1], 16;" :: "r"(smem_u32), "l"(gptr) : "memory")
#define CP_COMMIT() asm volatile("cp.async.commit_group;" ::: "memory")
#define CP_WAIT0()  asm volatile("cp.async.wait_group 0;" ::: "memory")

// ---------------- prep: B matrix + zero flags ----------------
__global__ void prep_kernel(const float* __restrict__ m_p, const float* __restrict__ logs_p) {
    int i = blockIdx.x * blockDim.x + threadIdx.x;   // over B*C*TX
    if (i >= B_ * C_ * TX_) return;
    if (i < B_ * 16) g_cnt[i] = 0;                   // reset producer flags every replay
    int s = i % TX_;
    int c = (i / TX_) % C_;
    int b = i / (TX_ * C_);
    float lg = logs_p[i];
    float mp = m_p[i];
    float se = expf(-2.0f * lg);
    g_B[(b * K2_ + c) * TX_ + s]        = se;
    g_B[(b * K2_ + C_ + c) * TX_ + s]   = se * mp;
}

// ---------------- prep: per-column constant ----------------
__global__ void cvec_kernel(const float* __restrict__ m_p, const float* __restrict__ logs_p) {
    int b = blockIdx.x;
    int s = threadIdx.x;                              // 512 threads
    float acc = 0.f;
    for (int c = 0; c < C_; c++) {
        int off = (b * C_ + c) * TX_ + s;
        float lg = logs_p[off];
        float mp = m_p[off];
        float se = expf(-2.0f * lg);
        acc += -0.5f * se * mp * mp - lg;
    }
    g_cvec[b * TX_ + s] = acc;
}

// ---------------- fused GEMM producer + DP consumer (512 threads/CTA) ----------------
#define BM 256
#define BN 128
#define BK 16

// DP row update; direction bit = sign of (v[j] - v[j-1]).
__device__ __forceinline__ void dp_row(float4 (&cur)[4], float (&v)[16],
                                       unsigned short* dirs, int t, int lane)
{
    float sh = __shfl_up_sync(0xffffffffu, v[15], 1);
    float left0 = (lane == 0) ? NEG_INF_ : sh;

    float r[16];
    r[0]=cur[0].x;  r[1]=cur[0].y;  r[2]=cur[0].z;  r[3]=cur[0].w;
    r[4]=cur[1].x;  r[5]=cur[1].y;  r[6]=cur[1].z;  r[7]=cur[1].w;
    r[8]=cur[2].x;  r[9]=cur[2].y;  r[10]=cur[2].z; r[11]=cur[2].w;
    r[12]=cur[3].x; r[13]=cur[3].y; r[14]=cur[3].z; r[15]=cur[3].w;

    unsigned bits = 0u;
#pragma unroll
    for (int j = 15; j >= 1; j--) {
        float left = v[j - 1];
        float d = v[j] - left;                     // sign=1 <=> left > v[j]
        bits |= (__float_as_uint(d) >> (31 - j)) & (1u << j);
        v[j] = r[j] + fmaxf(left, v[j]);
    }
    float d0 = v[0] - left0;
    bits |= (__float_as_uint(d0) >> 31);
    v[0] = r[0] + fmaxf(left0, v[0]);

    dirs[t * 32 + lane] = (unsigned short)bits;
}

// dynamic smem: dp CTA -> dirs(128KB) + rowbuf(64KB); gemm CTA -> As/Bs(48KB)
#define FUSED_SMEM (TY_ * 32 * 2 + 2 * CH_ * 128 * 16)

__global__ void __launch_bounds__(512) fused_kernel(const float* __restrict__ z_p,
                                                    const int* __restrict__ x_lengths,
                                                    const int* __restrict__ y_lengths)
{
    extern __shared__ char sdyn[];
    const int tid = threadIdx.x;

    if (blockIdx.x < B_) {
        // ================= DP consumer CTA (batch b) =================
        unsigned short* dirs = (unsigned short*)sdyn;                      // [TY_][32]
        float4* rowbuf = (float4*)(sdyn + (size_t)TY_ * 32 * 2);           // [2][CH_][128]

        const int b    = blockIdx.x;
        const int lane = tid & 31;
        const int w    = tid >> 5;                                         // 0..15
        const int t_x  = min(x_lengths[b], TX_);
        const int t_y  = min(y_lengths[b], TY_);
        const int nch  = (t_y + CH_ - 1) / CH_;                            // <= 128

        const float4* src = (const float4*)(g_negcent + (size_t)b * TY_ * TX_);
        const uint32_t rb_u32 = (uint32_t)__cvta_generic_to_shared(rowbuf);
        const int* cntb = g_cnt + b * 16;

        // ---- loader prologue: wait band 0 (rows 0..255), stream chunk 0 ----
        if (w > 0) {
            if (lane == 0) while (ld_acq(&cntb[0]) < 4) { }
            __syncwarp();
            const int lid = tid - 32;                                      // 0..479
            for (int p = lid; p < CH_ * 128; p += NLOAD_)
                CP_ASYNC16(rb_u32 + p * 16, src + (size_t)(p >> 7) * 128 + (p & 127));
            CP_COMMIT();
            CP_WAIT0();
        }

        float v[16];
#pragma unroll
        for (int j = 0; j < 16; j++) v[j] = NEG_INF_;
        if (tid == 0) v[0] = 0.0f;
        __syncthreads();

        for (int k = 0; k < nch; k++) {
            if (w > 0) {
                if (k + 1 < nch) {
                    const int c = k + 1;
                    if ((c & 15) == 0) {                                   // new 256-row band
                        if (lane == 0) while (ld_acq(&cntb[c >> 4]) < 4) { }
                        __syncwarp();
                    }
                    const int lid = tid - 32;
                    const int t0 = c * CH_;
                    const uint32_t dstb = rb_u32 + (uint32_t)((c & 1) * CH_ * 128 * 16);
                    for (int p = lid; p < CH_ * 128; p += NLOAD_)
                        CP_ASYNC16(dstb + p * 16, src + (size_t)(t0 + (p >> 7)) * 128 + (p & 127));
                    CP_COMMIT();
                    CP_WAIT0();
                }
            } else {
                const float4* bufb = rowbuf + (k & 1) * CH_ * 128 + lane * 4;
                const int tb = k * CH_;
                float4 cur[4], nxt[4];
                cur[0] = bufb[0]; cur[1] = bufb[1]; cur[2] = bufb[2]; cur[3] = bufb[3];
#pragma unroll
                for (int r = 0; r < CH_ - 1; r++) {
                    const float4* pn = bufb + (r + 1) * 128;
                    nxt[0] = pn[0]; nxt[1] = pn[1]; nxt[2] = pn[2]; nxt[3] = pn[3];
                    dp_row(cur, v, dirs, tb + r, lane);
                    cur[0] = nxt[0]; cur[1] = nxt[1]; cur[2] = nxt[2]; cur[3] = nxt[3];
                }
                dp_row(cur, v, dirs, tb + CH_ - 1, lane);
            }
            __syncthreads();
        }

        // rows >= t_y: no path
        for (int t = t_y + tid; t < TY_; t += 512) g_idx[b * TY_ + t] = -1;

        // backtrack (single lane)
        if (tid == 0) {
            int idx = t_x - 1;
            for (int j = t_y - 1; j >= 0; j--) {
                g_idx[b * TY_ + j] = idx;
                unsigned int word = dirs[j * 32 + (idx >> 4)];
                idx -= (int)((word >> (idx & 15)) & 1u);
            }
        }
        return;
    }

    // ================= GEMM producer CTA (512 threads, 256x128 tile) =================
    {
        const int r    = blockIdx.x - B_;
        const int nb   = r & 3;                   // 4 n-blocks
        const int b    = (r >> 2) & 15;           // 16 batches
        const int mblk = r >> 6;                  // 8 m-blocks of 256 rows (low bands first)
        const int m0   = mblk * BM;
        const int n0   = nb * BN;

        typedef float ATileT[BK][BM];
        typedef float BTileT[BK][BN];
        ATileT* As = (ATileT*)sdyn;                              // [2][16][256] 32KB
        BTileT* Bs = (BTileT*)(sdyn + 2 * BK * BM * 4);          // [2][16][128] 16KB

        const bool active = (m0 < y_lengths[b]) && (n0 < x_lengths[b]);

        if (active) {
            const int kRow   = tid >> 5;              // 0..15
            const int lbaseA = (tid & 31) << 3;       // 0..248 (8 floats)
            const int lbaseB = (tid & 31) << 2;       // 0..124 (4 floats)
            const int mBase  = (tid >> 4) << 3;       // 0..248
            const int nBase  = (tid & 15) << 3;       // 0..120

            const float* zpb = z_p + b * C_ * TY_;
            const float* Bb  = g_B + b * K2_ * TX_;

            F2 acc[8][4];
#pragma unroll
            for (int i = 0; i < 8; i++)
#pragma unroll
                for (int j = 0; j < 4; j++) { acc[i][j].f.x = 0.f; acc[i][j].f.y = 0.f; }

            float4 ra0, ra1, rb0;
            {
                int kk = kRow;
                int cA = (kk < C_) ? kk : kk - C_;
                const float* pA = zpb + cA * TY_ + m0 + lbaseA;
                ra0 = *(const float4*)pA;
                ra1 = *(const float4*)(pA + 4);
                if (kk < C_) {
                    ra0.x = -0.5f * ra0.x * ra0.x; ra0.y = -0.5f * ra0.y * ra0.y;
                    ra0.z = -0.5f * ra0.z * ra0.z; ra0.w = -0.5f * ra0.w * ra0.w;
                    ra1.x = -0.5f * ra1.x * ra1.x; ra1.y = -0.5f * ra1.y * ra1.y;
                    ra1.z = -0.5f * ra1.z * ra1.z; ra1.w = -0.5f * ra1.w * ra1.w;
                }
                rb0 = *(const float4*)(Bb + kk * TX_ + n0 + lbaseB);
            }
            *(float4*)&As[0][kRow][lbaseA]     = ra0;
            *(float4*)&As[0][kRow][lbaseA + 4] = ra1;
            *(float4*)&Bs[0][kRow][lbaseB]     = rb0;
            __syncthreads();

            const int NIT = K2_ / BK;   // 24
            for (int it = 0; it < NIT; ++it) {
                const int cur = it & 1;
                if (it + 1 < NIT) {
                    int kk = (it + 1) * BK + kRow;
                    int cA = (kk < C_) ? kk : kk - C_;
                    const float* pA = zpb + cA * TY_ + m0 + lbaseA;
                    ra0 = *(const float4*)pA;
                    ra1 = *(const float4*)(pA + 4);
                    if (kk < C_) {
                        ra0.x = -0.5f * ra0.x * ra0.x; ra0.y = -0.5f * ra0.y * ra0.y;
                        ra0.z = -0.5f * ra0.z * ra0.z; ra0.w = -0.5f * ra0.w * ra0.w;
                        ra1.x = -0.5f * ra1.x * ra1.x; ra1.y = -0.5f * ra1.y * ra1.y;
                        ra1.z = -0.5f * ra1.z * ra1.z; ra1.w = -0.5f * ra1.w * ra1.w;
                    }
                    rb0 = *(const float4*)(Bb + kk * TX_ + n0 + lbaseB);
                }
#pragma unroll
                for (int k = 0; k < BK; k++) {
                    float4 a0 = *(const float4*)&As[cur][k][mBase];
                    float4 a1 = *(const float4*)&As[cur][k][mBase + 4];
                    float4 b0 = *(const float4*)&Bs[cur][k][nBase];
                    float4 b1 = *(const float4*)&Bs[cur][k][nBase + 4];
                    F2 bb[4];
                    bb[0].f = make_float2(b0.x, b0.y);
                    bb[1].f = make_float2(b0.z, b0.w);
                    bb[2].f = make_float2(b1.x, b1.y);
                    bb[3].f = make_float2(b1.z, b1.w);
                    float a[8] = {a0.x, a0.y, a0.z, a0.w, a1.x, a1.y, a1.z, a1.w};
#pragma unroll
                    for (int i = 0; i < 8; i++) {
                        F2 aa; aa.f = make_float2(a[i], a[i]);
#pragma unroll
                        for (int j = 0; j < 4; j++)
                            acc[i][j].u = ffma2(aa.u, bb[j].u, acc[i][j].u);
                    }
                }
                if (it + 1 < NIT) {
                    const int nxt = cur ^ 1;
                    *(float4*)&As[nxt][kRow][lbaseA]     = ra0;
                    *(float4*)&As[nxt][kRow][lbaseA + 4] = ra1;
                    *(float4*)&Bs[nxt][kRow][lbaseB]     = rb0;
                }
                __syncthreads();
            }

            // epilogue: add per-column constant and store
            float4 cv0 = *(const float4*)(g_cvec + b * TX_ + n0 + nBase);
            float4 cv1 = *(const float4*)(g_cvec + b * TX_ + n0 + nBase + 4);
            float* outbase = g_negcent + ((size_t)b * TY_ + m0 + mBase) * TX_ + n0 + nBase;
#pragma unroll
            for (int i = 0; i < 8; i++) {
                float4 o0, o1;
                o0.x = acc[i][0].f.x + cv0.x; o0.y = acc[i][0].f.y + cv0.y;
                o0.z = acc[i][1].f.x + cv0.z; o0.w = acc[i][1].f.y + cv0.w;
                o1.x = acc[i][2].f.x + cv1.x; o1.y = acc[i][2].f.y + cv1.y;
                o1.z = acc[i][3].f.x + cv1.z; o1.w = acc[i][3].f.y + cv1.w;
                float* op = outbase + (size_t)i * TX_;
                *(float4*)op       = o0;
                *(float4*)(op + 4) = o1;
            }
            __syncthreads();
        }

        // signal band completion (also for skipped tiles)
        if (tid == 0) {
            __threadfence();
            atomicAdd(&g_cnt[b * 16 + mblk], 1);
        }
    }
}

// ---------------- attn output (one-hot rows) ----------------
__global__ void attn_kernel(float* __restrict__ out_attn) {
    const int rowid = blockIdx.x;           // b*2048 + t
    const int idx = g_idx[rowid];
    const int s0 = threadIdx.x * 4;         // 128 threads * 4 = 512
    float4 val = make_float4(0.f, 0.f, 0.f, 0.f);
    if (idx >= s0 && idx < s0 + 4) {
        if (idx == s0)          val.x = 1.f;
        else if (idx == s0 + 1) val.y = 1.f;
        else if (idx == s0 + 2) val.z = 1.f;
        else                    val.w = 1.f;
    }
    *(float4*)(out_attn + (size_t)rowid * TX_ + s0) = val;
}

// ---------------- gathered m_p / logs_p ----------------
__global__ void gather_kernel(const float* __restrict__ m_p, const float* __restrict__ logs_p,
                              float* __restrict__ out_m, float* __restrict__ out_l)
{
    int i = blockIdx.x * blockDim.x + threadIdx.x;  // over B*C*TY
    if (i >= B_ * C_ * TY_) return;
    int t = i % TY_;
    int c = (i / TY_) % C_;
    int b = i / (TY_ * C_);
    int idx = g_idx[b * TY_ + t];
    float vm = 0.f, vl = 0.f;
    if (idx >= 0) {
        int off = (b * C_ + c) * TX_ + idx;
        vm = m_p[off];
        vl = logs_p[off];
    }
    out_m[i] = vm;
    out_l[i] = vl;
}

// ---------------- random segment slice ----------------
__global__ void zslice_kernel(const float* __restrict__ z, const int* __restrict__ y_lengths,
                              const float* __restrict__ rand_u,
                              float* __restrict__ out_z, float* __restrict__ out_ids)
{
    int i = blockIdx.x * blockDim.x + threadIdx.x;  // over B*C*SEG
    if (i >= B_ * C_ * SEG_) return;
    int k = i % SEG_;
    int c = (i / SEG_) % C_;
    int b = i / (SEG_ * C_);
    int safe  = min(y_lengths[b], TY_);
    int idmax = max(safe - SEG_, 0);
    int ids   = (int)(rand_u[b] * ((float)idmax + 1e-8f));
    float vv = z[(b * C_ + c) * TY_ + ids + k];
    out_z[i] = (k < safe - ids) ? vv : 0.f;
    if (i < B_) {
        int sb = min(y_lengths[i], TY_);
        int im = max(sb - SEG_, 0);
        out_ids[i] = (float)((int)(rand_u[i] * ((float)im + 1e-8f)));
    }
}

// ---------------- launcher ----------------
extern "C" void kernel_launch(void* const* d_in, const int* in_sizes, int n_in,
                              void* d_out, int out_size)
{
    const float* z         = (const float*)d_in[0];
    const float* z_p       = (const float*)d_in[1];
    const float* m_p       = (const float*)d_in[2];
    const float* logs_p    = (const float*)d_in[3];
    const int*   x_lengths = (const int*)d_in[4];
    const int*   y_lengths = (const int*)d_in[5];
    const float* rand_u    = (const float*)d_in[6];

    float* out      = (float*)d_out;
    float* out_z    = out;                   // 16*192*32      = 98304
    float* out_ids  = out + 98304;           // 16
    float* out_attn = out + 98320;           // 16*2048*512    = 16777216
    float* out_m    = out + 16875536;        // 16*192*2048    = 6291456
    float* out_l    = out + 23166992;        // 16*192*2048    = 6291456
    (void)in_sizes; (void)n_in; (void)out_size;

    prep_kernel<<<(B_ * C_ * TX_ + 255) / 256, 256>>>(m_p, logs_p);
    cvec_kernel<<<B_, TX_>>>(m_p, logs_p);

    cudaFuncSetAttribute(fused_kernel, cudaFuncAttributeMaxDynamicSharedMemorySize, FUSED_SMEM);
    fused_kernel<<<B_ + 4 * 16 * 8, 512, FUSED_SMEM>>>(z_p, x_lengths, y_lengths);

    attn_kernel<<<B_ * TY_, TX_ / 4>>>(out_attn);
    gather_kernel<<<(B_ * C_ * TY_ + 255) / 256, 256>>>(m_p, logs_p, out_m, out_l);
    zslice_kernel<<<(B_ * C_ * SEG_ + 255) / 256, 256>>>(z, y_lengths, rand_u, out_z, out_ids);
}

// round 12
// speedup vs baseline: 1.0582x; 1.0582x over previous
#include <cuda_runtime.h>
#include <cuda_bf16.h>
#include <cstdint>

#define B_   16
#define C_   192
#define TX_  512
#define TY_  2048
#define SEG_ 32
#define K2_  384          // 2*C
#define NEG_INF_ (-1e9f)
#define CH_  16           // DP chunk rows staged in smem per phase
#define NLOAD_ 480        // dp loader lanes (15 warps)

// grid layout of fused kernel
#define GEMM0_   (B_)                 // 16
#define NGEMM_   (4 * 16 * 8)         // 512
#define EPI0_    (GEMM0_ + NGEMM_)    // 528
#define EPB_     64                   // epilogue CTAs per batch
#define NEPI_    (B_ * EPB_)          // 1024
#define ZSL0_    (EPI0_ + NEPI_)      // 1552
#define NCTAS_   (ZSL0_ + B_)         // 1568

// ---------------- scratch (device globals: no runtime allocation) ----------------
__device__ float g_B[B_ * K2_ * TX_];
__device__ float g_cvec[B_ * TX_];
__device__ float g_negcent[(size_t)B_ * TY_ * TX_];  // 64 MB
__device__ int   g_idx[B_ * TY_];
__device__ int   g_cnt[B_ * 16];                     // per (b, 256-row band) completed n-tiles (target 4)
__device__ int   g_done[B_];                         // dp finished (g_idx valid) per batch

// ---------------- helpers ----------------
union F2 { float2 f; unsigned long long u; };

__device__ __forceinline__ unsigned long long ffma2(unsigned long long a,
                                                    unsigned long long b,
                                                    unsigned long long c) {
    unsigned long long d;
    asm("fma.rn.f32x2 %0, %1, %2, %3;" : "=l"(d) : "l"(a), "l"(b), "l"(c));
    return d;
}

__device__ __forceinline__ int ld_acq(const int* p) {
    int v;
    asm volatile("ld.acquire.gpu.global.b32 %0, [%1];" : "=r"(v) : "l"(p) : "memory");
    return v;
}
__device__ __forceinline__ void st_rel(int* p, int v) {
    asm volatile("st.release.gpu.global.b32 [%0], %1;" :: "l"(p), "r"(v) : "memory");
}

#define CP_ASYNC16(smem_u32, gptr) \
    asm volatile("cp.async.cg.shared.global [%0], [%1], 16;" :: "r"(smem_u32), "l"(gptr) : "memory")
#define CP_COMMIT() asm volatile("cp.async.commit_group;" ::: "memory")
#define CP_WAIT0()  asm volatile("cp.async.wait_group 0;" ::: "memory")

// ---------------- prep: B matrix + zero flags ----------------
__global__ void prep_kernel(const float* __restrict__ m_p, const float* __restrict__ logs_p) {
    int i = blockIdx.x * blockDim.x + threadIdx.x;   // over B*C*TX
    if (i >= B_ * C_ * TX_) return;
    if (i < B_ * 16) g_cnt[i] = 0;                   // reset producer flags every replay
    if (i < B_) g_done[i] = 0;
    int s = i % TX_;
    int c = (i / TX_) % C_;
    int b = i / (TX_ * C_);
    float lg = logs_p[i];
    float mp = m_p[i];
    float se = expf(-2.0f * lg);
    g_B[(b * K2_ + c) * TX_ + s]        = se;
    g_B[(b * K2_ + C_ + c) * TX_ + s]   = se * mp;
}

// ---------------- prep: per-column constant ----------------
__global__ void cvec_kernel(const float* __restrict__ m_p, const float* __restrict__ logs_p) {
    int b = blockIdx.x;
    int s = threadIdx.x;                              // 512 threads
    float acc = 0.f;
    for (int c = 0; c < C_; c++) {
        int off = (b * C_ + c) * TX_ + s;
        float lg = logs_p[off];
        float mp = m_p[off];
        float se = expf(-2.0f * lg);
        acc += -0.5f * se * mp * mp - lg;
    }
    g_cvec[b * TX_ + s] = acc;
}

// ---------------- fused GEMM producer + DP consumer + gated epilogues ----------------
#define BM 256
#define BN 128
#define BK 16

// DP row update; direction bit = sign of (v[j] - v[j-1]).
__device__ __forceinline__ void dp_row(float4 (&cur)[4], float (&v)[16],
                                       unsigned short* dirs, int t, int lane)
{
    float sh = __shfl_up_sync(0xffffffffu, v[15], 1);
    float left0 = (lane == 0) ? NEG_INF_ : sh;

    float r[16];
    r[0]=cur[0].x;  r[1]=cur[0].y;  r[2]=cur[0].z;  r[3]=cur[0].w;
    r[4]=cur[1].x;  r[5]=cur[1].y;  r[6]=cur[1].z;  r[7]=cur[1].w;
    r[8]=cur[2].x;  r[9]=cur[2].y;  r[10]=cur[2].z; r[11]=cur[2].w;
    r[12]=cur[3].x; r[13]=cur[3].y; r[14]=cur[3].z; r[15]=cur[3].w;

    unsigned bits = 0u;
#pragma unroll
    for (int j = 15; j >= 1; j--) {
        float left = v[j - 1];
        float d = v[j] - left;                     // sign=1 <=> left > v[j]
        bits |= (__float_as_uint(d) >> (31 - j)) & (1u << j);
        v[j] = r[j] + fmaxf(left, v[j]);
    }
    float d0 = v[0] - left0;
    bits |= (__float_as_uint(d0) >> 31);
    v[0] = r[0] + fmaxf(left0, v[0]);

    dirs[t * 32 + lane] = (unsigned short)bits;
}

// dynamic smem: dp CTA -> dirs(128KB) + rowbuf(64KB); gemm CTA -> As/Bs(48KB)
#define FUSED_SMEM (TY_ * 32 * 2 + 2 * CH_ * 128 * 16)

__global__ void __launch_bounds__(512) fused_kernel(const float* __restrict__ z_p,
                                                    const float* __restrict__ m_p,
                                                    const float* __restrict__ logs_p,
                                                    const float* __restrict__ z,
                                                    const int* __restrict__ x_lengths,
                                                    const int* __restrict__ y_lengths,
                                                    const float* __restrict__ rand_u,
                                                    float* __restrict__ out_z,
                                                    float* __restrict__ out_ids,
                                                    float* __restrict__ out_attn,
                                                    float* __restrict__ out_m,
                                                    float* __restrict__ out_l)
{
    extern __shared__ char sdyn[];
    const int tid = threadIdx.x;
    const unsigned bid = blockIdx.x;

    if (bid < GEMM0_) {
        // ================= DP consumer CTA (batch b) =================
        unsigned short* dirs = (unsigned short*)sdyn;                      // [TY_][32]
        float4* rowbuf = (float4*)(sdyn + (size_t)TY_ * 32 * 2);           // [2][CH_][128]

        const int b    = bid;
        const int lane = tid & 31;
        const int w    = tid >> 5;                                         // 0..15
        const int t_x  = min(x_lengths[b], TX_);
        const int t_y  = min(y_lengths[b], TY_);
        const int nch  = (t_y + CH_ - 1) / CH_;                            // <= 128

        const float4* src = (const float4*)(g_negcent + (size_t)b * TY_ * TX_);
        const uint32_t rb_u32 = (uint32_t)__cvta_generic_to_shared(rowbuf);
        const int* cntb = g_cnt + b * 16;

        // ---- loader prologue: wait band 0 (rows 0..255), stream chunk 0 ----
        if (w > 0) {
            if (lane == 0) while (ld_acq(&cntb[0]) < 4) { }
            __syncwarp();
            const int lid = tid - 32;                                      // 0..479
            for (int p = lid; p < CH_ * 128; p += NLOAD_)
                CP_ASYNC16(rb_u32 + p * 16, src + (size_t)(p >> 7) * 128 + (p & 127));
            CP_COMMIT();
            CP_WAIT0();
        }

        float v[16];
#pragma unroll
        for (int j = 0; j < 16; j++) v[j] = NEG_INF_;
        if (tid == 0) v[0] = 0.0f;
        __syncthreads();

        for (int k = 0; k < nch; k++) {
            if (w > 0) {
                if (k + 1 < nch) {
                    const int c = k + 1;
                    if ((c & 15) == 0) {                                   // new 256-row band
                        if (lane == 0) while (ld_acq(&cntb[c >> 4]) < 4) { }
                        __syncwarp();
                    }
                    const int lid = tid - 32;
                    const int t0 = c * CH_;
                    const uint32_t dstb = rb_u32 + (uint32_t)((c & 1) * CH_ * 128 * 16);
                    for (int p = lid; p < CH_ * 128; p += NLOAD_)
                        CP_ASYNC16(dstb + p * 16, src + (size_t)(t0 + (p >> 7)) * 128 + (p & 127));
                    CP_COMMIT();
                    CP_WAIT0();
                }
            } else {
                const float4* bufb = rowbuf + (k & 1) * CH_ * 128 + lane * 4;
                const int tb = k * CH_;
                float4 cur[4], nxt[4];
                cur[0] = bufb[0]; cur[1] = bufb[1]; cur[2] = bufb[2]; cur[3] = bufb[3];
#pragma unroll
                for (int r = 0; r < CH_ - 1; r++) {
                    const float4* pn = bufb + (r + 1) * 128;
                    nxt[0] = pn[0]; nxt[1] = pn[1]; nxt[2] = pn[2]; nxt[3] = pn[3];
                    dp_row(cur, v, dirs, tb + r, lane);
                    cur[0] = nxt[0]; cur[1] = nxt[1]; cur[2] = nxt[2]; cur[3] = nxt[3];
                }
                dp_row(cur, v, dirs, tb + CH_ - 1, lane);
            }
            __syncthreads();
        }

        // rows >= t_y: no path
        for (int t = t_y + tid; t < TY_; t += 512) g_idx[b * TY_ + t] = -1;

        // backtrack (single lane), then publish
        __syncthreads();
        if (tid == 0) {
            int idx = t_x - 1;
            for (int j = t_y - 1; j >= 0; j--) {
                g_idx[b * TY_ + j] = idx;
                unsigned int word = dirs[j * 32 + (idx >> 4)];
                idx -= (int)((word >> (idx & 15)) & 1u);
            }
            __threadfence();
            st_rel(&g_done[b], 1);
        }
        return;
    }

    if (bid < EPI0_) {
        // ================= GEMM producer CTA (512 threads, 256x128 tile) =================
        const int r    = bid - GEMM0_;
        const int nb   = r & 3;                   // 4 n-blocks
        const int b    = (r >> 2) & 15;           // 16 batches
        const int mblk = r >> 6;                  // 8 m-blocks of 256 rows (low bands first)
        const int m0   = mblk * BM;
        const int n0   = nb * BN;

        typedef float ATileT[BK][BM];
        typedef float BTileT[BK][BN];
        ATileT* As = (ATileT*)sdyn;                              // [2][16][256] 32KB
        BTileT* Bs = (BTileT*)(sdyn + 2 * BK * BM * 4);          // [2][16][128] 16KB

        const bool active = (m0 < y_lengths[b]) && (n0 < x_lengths[b]);

        if (active) {
            const int kRow   = tid >> 5;              // 0..15
            const int lbaseA = (tid & 31) << 3;       // 0..248
            const int lbaseB = (tid & 31) << 2;       // 0..124
            const int mBase  = (tid >> 4) << 3;       // 0..248
            const int nBase  = (tid & 15) << 3;       // 0..120

            const float* zpb = z_p + b * C_ * TY_;
            const float* Bb  = g_B + b * K2_ * TX_;

            F2 acc[8][4];
#pragma unroll
            for (int i = 0; i < 8; i++)
#pragma unroll
                for (int j = 0; j < 4; j++) { acc[i][j].f.x = 0.f; acc[i][j].f.y = 0.f; }

            float4 ra0, ra1, rb0;
            {
                int kk = kRow;
                int cA = (kk < C_) ? kk : kk - C_;
                const float* pA = zpb + cA * TY_ + m0 + lbaseA;
                ra0 = *(const float4*)pA;
                ra1 = *(const float4*)(pA + 4);
                if (kk < C_) {
                    ra0.x = -0.5f * ra0.x * ra0.x; ra0.y = -0.5f * ra0.y * ra0.y;
                    ra0.z = -0.5f * ra0.z * ra0.z; ra0.w = -0.5f * ra0.w * ra0.w;
                    ra1.x = -0.5f * ra1.x * ra1.x; ra1.y = -0.5f * ra1.y * ra1.y;
                    ra1.z = -0.5f * ra1.z * ra1.z; ra1.w = -0.5f * ra1.w * ra1.w;
                }
                rb0 = *(const float4*)(Bb + kk * TX_ + n0 + lbaseB);
            }
            *(float4*)&As[0][kRow][lbaseA]     = ra0;
            *(float4*)&As[0][kRow][lbaseA + 4] = ra1;
            *(float4*)&Bs[0][kRow][lbaseB]     = rb0;
            __syncthreads();

            const int NIT = K2_ / BK;   // 24
            for (int it = 0; it < NIT; ++it) {
                const int cur = it & 1;
                if (it + 1 < NIT) {
                    int kk = (it + 1) * BK + kRow;
                    int cA = (kk < C_) ? kk : kk - C_;
                    const float* pA = zpb + cA * TY_ + m0 + lbaseA;
                    ra0 = *(const float4*)pA;
                    ra1 = *(const float4*)(pA + 4);
                    if (kk < C_) {
                        ra0.x = -0.5f * ra0.x * ra0.x; ra0.y = -0.5f * ra0.y * ra0.y;
                        ra0.z = -0.5f * ra0.z * ra0.z; ra0.w = -0.5f * ra0.w * ra0.w;
                        ra1.x = -0.5f * ra1.x * ra1.x; ra1.y = -0.5f * ra1.y * ra1.y;
                        ra1.z = -0.5f * ra1.z * ra1.z; ra1.w = -0.5f * ra1.w * ra1.w;
                    }
                    rb0 = *(const float4*)(Bb + kk * TX_ + n0 + lbaseB);
                }
#pragma unroll
                for (int k = 0; k < BK; k++) {
                    float4 a0 = *(const float4*)&As[cur][k][mBase];
                    float4 a1 = *(const float4*)&As[cur][k][mBase + 4];
                    float4 b0 = *(const float4*)&Bs[cur][k][nBase];
                    float4 b1 = *(const float4*)&Bs[cur][k][nBase + 4];
                    F2 bb[4];
                    bb[0].f = make_float2(b0.x, b0.y);
                    bb[1].f = make_float2(b0.z, b0.w);
                    bb[2].f = make_float2(b1.x, b1.y);
                    bb[3].f = make_float2(b1.z, b1.w);
                    float a[8] = {a0.x, a0.y, a0.z, a0.w, a1.x, a1.y, a1.z, a1.w};
#pragma unroll
                    for (int i = 0; i < 8; i++) {
                        F2 aa; aa.f = make_float2(a[i], a[i]);
#pragma unroll
                        for (int j = 0; j < 4; j++)
                            acc[i][j].u = ffma2(aa.u, bb[j].u, acc[i][j].u);
                    }
                }
                if (it + 1 < NIT) {
                    const int nxt = cur ^ 1;
                    *(float4*)&As[nxt][kRow][lbaseA]     = ra0;
                    *(float4*)&As[nxt][kRow][lbaseA + 4] = ra1;
                    *(float4*)&Bs[nxt][kRow][lbaseB]     = rb0;
                }
                __syncthreads();
            }

            // epilogue: add per-column constant and store
            float4 cv0 = *(const float4*)(g_cvec + b * TX_ + n0 + nBase);
            float4 cv1 = *(const float4*)(g_cvec + b * TX_ + n0 + nBase + 4);
            float* outbase = g_negcent + ((size_t)b * TY_ + m0 + mBase) * TX_ + n0 + nBase;
#pragma unroll
            for (int i = 0; i < 8; i++) {
                float4 o0, o1;
                o0.x = acc[i][0].f.x + cv0.x; o0.y = acc[i][0].f.y + cv0.y;
                o0.z = acc[i][1].f.x + cv0.z; o0.w = acc[i][1].f.y + cv0.w;
                o1.x = acc[i][2].f.x + cv1.x; o1.y = acc[i][2].f.y + cv1.y;
                o1.z = acc[i][3].f.x + cv1.z; o1.w = acc[i][3].f.y + cv1.w;
                float* op = outbase + (size_t)i * TX_;
                *(float4*)op       = o0;
                *(float4*)(op + 4) = o1;
            }
            __syncthreads();
        }

        // signal band completion (also for skipped tiles)
        if (tid == 0) {
            __threadfence();
            atomicAdd(&g_cnt[b * 16 + mblk], 1);
        }
        return;
    }

    if (bid < ZSL0_) {
        // ================= gated epilogue CTA: attn rows + m/logs gathers =================
        const int e    = bid - EPI0_;
        const int b    = e >> 6;                  // 64 CTAs per batch
        const int part = e & 63;

        __shared__ int s_ready;
        if (tid == 0) {
            while (ld_acq(&g_done[b]) == 0) { }
            s_ready = 1;
        }
        __syncthreads();
        (void)s_ready;

        // attn: rows [part*32, part*32+32), 512x4 floats per row
        {
            const int base = b * TY_ + part * 32;
#pragma unroll
            for (int i = 0; i < 8; i++) {
                int p   = tid + i * 512;              // 0..4095
                int t   = base + (p >> 7);
                int c4  = p & 127;
                int idx = g_idx[t];
                int s0  = c4 * 4;
                float4 val = make_float4(0.f, 0.f, 0.f, 0.f);
                if (idx >= s0 && idx < s0 + 4) {
                    if (idx == s0)          val.x = 1.f;
                    else if (idx == s0 + 1) val.y = 1.f;
                    else if (idx == s0 + 2) val.z = 1.f;
                    else                    val.w = 1.f;
                }
                *(float4*)(out_attn + (size_t)t * TX_ + s0) = val;
            }
        }

        // gather: elements [part*6144, part*6144+6144) of batch b's 192*2048
        {
            const int ebase = part * 6144;
#pragma unroll
            for (int i = 0; i < 12; i++) {
                int p = ebase + tid + i * 512;
                int t = p & (TY_ - 1);
                int c = p >> 11;                      // /2048
                int idx = g_idx[b * TY_ + t];
                float vm = 0.f, vl = 0.f;
                if (idx >= 0) {
                    int off = (b * C_ + c) * TX_ + idx;
                    vm = m_p[off];
                    vl = logs_p[off];
                }
                int o = (b * C_ + c) * TY_ + t;
                out_m[o] = vm;
                out_l[o] = vl;
            }
        }
        return;
    }

    // ================= zslice CTA (one per batch, no dp dependency) =================
    {
        const int b = bid - ZSL0_;
        int safe  = min(y_lengths[b], TY_);
        int idmax = max(safe - SEG_, 0);
        int ids   = (int)(rand_u[b] * ((float)idmax + 1e-8f));
        if (tid == 0) out_ids[b] = (float)ids;
        // C_*SEG_ = 6144 elements
#pragma unroll
        for (int i = 0; i < 12; i++) {
            int p = tid + i * 512;
            int k = p & (SEG_ - 1);
            int c = p >> 5;
            float vv = z[(b * C_ + c) * TY_ + ids + k];
            out_z[(b * C_ + c) * SEG_ + k] = (k < safe - ids) ? vv : 0.f;
        }
    }
}

// ---------------- launcher ----------------
extern "C" void kernel_launch(void* const* d_in, const int* in_sizes, int n_in,
                              void* d_out, int out_size)
{
    const float* z         = (const float*)d_in[0];
    const float* z_p       = (const float*)d_in[1];
    const float* m_p       = (const float*)d_in[2];
    const float* logs_p    = (const float*)d_in[3];
    const int*   x_lengths = (const int*)d_in[4];
    const int*   y_lengths = (const int*)d_in[5];
    const float* rand_u    = (const float*)d_in[6];

    float* out      = (float*)d_out;
    float* out_z    = out;                   // 16*192*32      = 98304
    float* out_ids  = out + 98304;           // 16
    float* out_attn = out + 98320;           // 16*2048*512    = 16777216
    float* out_m    = out + 16875536;        // 16*192*2048    = 6291456
    float* out_l    = out + 23166992;        // 16*192*2048    = 6291456
    (void)in_sizes; (void)n_in; (void)out_size;

    prep_kernel<<<(B_ * C_ * TX_ + 255) / 256, 256>>>(m_p, logs_p);
    cvec_kernel<<<B_, TX_>>>(m_p, logs_p);

    cudaFuncSetAttribute(fused_kernel, cudaFuncAttributeMaxDynamicSharedMemorySize, FUSED_SMEM);
    fused_kernel<<<NCTAS_, 512, FUSED_SMEM>>>(z_p, m_p, logs_p, z,
                                              x_lengths, y_lengths, rand_u,
                                              out_z, out_ids, out_attn, out_m, out_l);
}